// round 14
// baseline (speedup 1.0000x reference)
#include <cuda_runtime.h>

#define NC 4096
#define NA 2048
#define NB (NC + NA)          // 6144 bodies
#define TPB 128
#define ITILES (NB / TPB)     // 48 i-tiles (0..31 circle, 32..47 aabb)
#define CHUNK 128             // j-chunk size
#define NCY (NC / CHUNK)      // 32 circle j-chunks
#define NAY (NA / CHUNK)      // 16 aabb j-chunks
#define NJY (NCY + NAY)       // 48 j-chunks
#define EPSF 1e-9f

// partial corrections: [NJY][NB] float2
__device__ float2 g_partial[NJY * NB];
__device__ int    g_cnt[ITILES] = {};

typedef unsigned long long u64;

__device__ __forceinline__ float rsq_approx(float x) {
    float r;
    asm("rsqrt.approx.f32 %0, %1;" : "=f"(r) : "f"(x));
    return r;
}
__device__ __forceinline__ u64 pack2(float lo, float hi) {
    u64 r; asm("mov.b64 %0, {%1, %2};" : "=l"(r) : "f"(lo), "f"(hi)); return r;
}
__device__ __forceinline__ void unpack2(u64 v, float& lo, float& hi) {
    asm("mov.b64 {%0, %1}, %2;" : "=f"(lo), "=f"(hi) : "l"(v));
}
__device__ __forceinline__ u64 add2(u64 a, u64 b) {
    u64 r; asm("add.rn.f32x2 %0, %1, %2;" : "=l"(r) : "l"(a), "l"(b)); return r;
}
__device__ __forceinline__ u64 fma2(u64 a, u64 b, u64 c) {
    u64 r; asm("fma.rn.f32x2 %0, %1, %2, %3;" : "=l"(r) : "l"(a), "l"(b), "l"(c)); return r;
}

__global__ void __launch_bounds__(TPB)
collide_kernel(const float* __restrict__ cpos, const float* __restrict__ crad,
               const float* __restrict__ apos, const float* __restrict__ ahalf,
               float* __restrict__ out)
{
    // one float4 per j-body: circle (−x, −y, 0.5*r, 0) ; aabb (−x, −y, hx, hy)
    __shared__ float4 sj[CHUNK];
    __shared__ int s_old;

    const int tid = threadIdx.x;
    const int bx  = blockIdx.y;                 // i-tile   (swapped for wave mixing)
    const int jy  = blockIdx.x;                 // j-chunk
    const int i   = bx * TPB + tid;             // body index 0..NB-1
    const bool i_is_circle = (i < NC);
    const bool j_is_circle = (jy < NCY);
    const int j0 = j_is_circle ? (jy * CHUNK) : ((jy - NCY) * CHUNK);
    const bool diag = (bx == jy);               // aligned 128-tiles: same bodies

    // stage CHUNK j-bodies (one per thread), positions negated
    {
        if (j_is_circle) {
            float2 p = ((const float2*)cpos)[j0 + tid];
            sj[tid] = make_float4(-p.x, -p.y, 0.5f * crad[j0 + tid], 0.0f);
        } else {
            float2 p = ((const float2*)apos)[j0 + tid];
            float2 h = ((const float2*)ahalf)[j0 + tid];
            sj[tid] = make_float4(-p.x, -p.y, h.x, h.y);
        }
    }

    // hoisted i-state
    float pix, piy, ra, rb;      // circle: ra=0.5*r ; aabb: ra=hx, rb=hy
    int ia = 0;
    if (i_is_circle) {
        float2 p = ((const float2*)cpos)[i];
        pix = p.x; piy = p.y;
        ra = 0.5f * crad[i]; rb = 0.0f;
    } else {
        ia = i - NC;
        float2 p = ((const float2*)apos)[ia];
        float2 h = ((const float2*)ahalf)[ia];
        pix = p.x; piy = p.y;
        ra = h.x; rb = h.y;
    }
    const float nra = -ra, nrb = -rb;
    const u64 pixy = pack2(pix, piy);

    __syncthreads();

    u64 acc = pack2(0.0f, 0.0f);

    if (i_is_circle) {
        if (j_is_circle) {
            if (diag) {
                // cc diagonal: EPS clamp => self-pair contributes exactly 0
                #pragma unroll 16
                for (int k = 0; k < CHUNK; k++) {
                    float4 b = sj[k];
                    u64 d = add2(pixy, pack2(b.x, b.y));
                    float dx, dy; unpack2(d, dx, dy);
                    float d2 = fmaxf(fmaf(dx, dx, dy * dy), EPSF);
                    float inv = rsq_approx(d2);
                    float s = fmaxf(fmaf(ra + b.z, inv, -0.5f), 0.0f);
                    acc = fma2(pack2(s, s), d, acc);
                }
            } else {
                // cc off-diagonal: distinct random bodies => d2 > 0, no clamp
                #pragma unroll 16
                for (int k = 0; k < CHUNK; k++) {
                    float4 b = sj[k];
                    u64 d = add2(pixy, pack2(b.x, b.y));
                    float dx, dy; unpack2(d, dx, dy);
                    float d2 = fmaf(dx, dx, dy * dy);
                    float inv = rsq_approx(d2);
                    float s = fmaxf(fmaf(ra + b.z, inv, -0.5f), 0.0f);
                    acc = fma2(pack2(s, s), d, acc);
                }
            }
        } else {
            // circle vs aabb (push on circle) — clamp required (center-in-box => dd2=0)
            #pragma unroll 16
            for (int k = 0; k < CHUNK; k++) {
                float4 b = sj[k];
                u64 rel = add2(pixy, pack2(b.x, b.y));  // ci - aj
                float rx, ry; unpack2(rel, rx, ry);
                float dx = rx - fminf(fmaxf(rx, -b.z), b.z);
                float dy = ry - fminf(fmaxf(ry, -b.w), b.w);
                float dd2 = fmaxf(fmaf(dx, dx, dy * dy), EPSF);
                float inv = rsq_approx(dd2);
                float s = fmaxf(fmaf(ra, inv, -0.5f), 0.0f);   // ra = 0.5*ri
                acc = fma2(pack2(s, s), pack2(dx, dy), acc);
            }
        }
    } else {
        if (j_is_circle) {
            // aabb vs circle: rel' = ai - cj = -rel => box push = +s*diff'
            #pragma unroll 16
            for (int k = 0; k < CHUNK; k++) {
                float4 b = sj[k];
                u64 rel = add2(pixy, pack2(b.x, b.y));  // ai - cj
                float rx, ry; unpack2(rel, rx, ry);
                float dx = rx - fminf(fmaxf(rx, nra), ra);    // ra=hx
                float dy = ry - fminf(fmaxf(ry, nrb), rb);    // rb=hy
                float dd2 = fmaxf(fmaf(dx, dx, dy * dy), EPSF);
                float inv = rsq_approx(dd2);
                float s = fmaxf(fmaf(b.z, inv, -0.5f), 0.0f); // b.z = 0.5*rj
                acc = fma2(pack2(s, s), pack2(dx, dy), acc);
            }
        } else {
            float cx = 0.0f, cy = 0.0f;
            if (diag) {
                // aa diagonal: guard self-pair
                #pragma unroll 16
                for (int k = 0; k < CHUNK; k++) {
                    float4 b = sj[k];
                    int j = j0 + k;
                    u64 da = add2(pixy, pack2(b.x, b.y));
                    float dax, day; unpack2(da, dax, day);
                    float ovx = (ra + b.z) - fabsf(dax);
                    float ovy = (rb + b.w) - fabsf(day);
                    bool hit = (ovx > 0.0f) && (ovy > 0.0f) && (ia != j);
                    bool usex = (ovx <= ovy);
                    cx += (hit && usex)  ? copysignf(0.5f * ovx, dax) : 0.0f;
                    cy += (hit && !usex) ? copysignf(0.5f * ovy, day) : 0.0f;
                }
            } else {
                // aa off-diagonal: no self-pair possible
                #pragma unroll 16
                for (int k = 0; k < CHUNK; k++) {
                    float4 b = sj[k];
                    u64 da = add2(pixy, pack2(b.x, b.y));
                    float dax, day; unpack2(da, dax, day);
                    float ovx = (ra + b.z) - fabsf(dax);
                    float ovy = (rb + b.w) - fabsf(day);
                    bool hit = (ovx > 0.0f) && (ovy > 0.0f);
                    bool usex = (ovx <= ovy);
                    cx += (hit && usex)  ? copysignf(0.5f * ovx, dax) : 0.0f;
                    cy += (hit && !usex) ? copysignf(0.5f * ovy, day) : 0.0f;
                }
            }
            acc = pack2(cx, cy);
        }
    }

    {
        float ax, ay; unpack2(acc, ax, ay);
        g_partial[(size_t)jy * NB + i] = make_float2(ax, ay);
    }

    // ---- last-arriving block of this i-tile folds all partials (fixed order) ----
    __threadfence();                       // release partial write
    if (tid == 0) s_old = atomicAdd(&g_cnt[bx], 1);
    __syncthreads();
    if (s_old == NJY - 1) {
        __threadfence();                   // see all partials
        float2 base = i_is_circle ? ((const float2*)cpos)[i]
                                  : ((const float2*)apos)[i - NC];
        float sx = base.x, sy = base.y;
        #pragma unroll
        for (int y = 0; y < NJY; y++) {    // fixed order => deterministic
            float2 p = g_partial[(size_t)y * NB + i];
            sx += p.x; sy += p.y;
        }
        ((float2*)out)[i] = make_float2(sx, sy);
        if (tid == 0) g_cnt[bx] = 0;       // reset for next graph replay
    }
}

extern "C" void kernel_launch(void* const* d_in, const int* in_sizes, int n_in,
                              void* d_out, int out_size)
{
    const float* cpos  = (const float*)d_in[0];   // [4096,2]
    const float* crad  = (const float*)d_in[1];   // [4096]
    const float* apos  = (const float*)d_in[2];   // [2048,2]
    const float* ahalf = (const float*)d_in[3];   // [2048,2]
    float* out = (float*)d_out;                   // [6144,2]

    dim3 grid(NJY, ITILES);                       // x = j-chunk: wave-mixes block costs
    collide_kernel<<<grid, TPB>>>(cpos, crad, apos, ahalf, out);
}